// round 17
// baseline (speedup 1.0000x reference)
#include <cuda_runtime.h>
#include <cuda_fp16.h>
#include <math.h>
#include <stdint.h>

#define T_TOK   32768
#define DIM     512
#define SCALE_F 0.125f

#define PITCHB  80
#define NKT     16                         // 512 / 32

// ---- shared tile geometry: CTA 128 x 256, 8 warps of 64x64, 3-stage ----
#define A1TILE  (128 * PITCHB)            // 10240 B
#define B1TILE  (256 * PITCHB)            // 20480 B
#define STAGE1  (A1TILE + B1TILE)         // 30720 B
#define NSTG1   3
#define SMEM1_BYTES (NSTG1 * STAGE1)      // 92160 B/CTA, 2 CTAs/SM

// ------------------------- device scratch (fp16 operands) -------------------------
__device__ __half g_xh [(size_t)T_TOK * DIM];   // x in fp16
__device__ __half g_Oh [(size_t)T_TOK * DIM];   // softmax*v in fp16
__device__ __half g_W2h[1024 * DIM];            // [n][k], n = h*128 + (z:0-63 | v:64-127)
__device__ __half g_Wph[DIM * DIM];             // Wp^T [n][k]
__device__ float g_bz[DIM];
__device__ float g_bv[DIM];

// ------------------------- helpers -------------------------
__device__ __forceinline__ uint32_t smem_u32(const void* p) {
    uint32_t a;
    asm("{ .reg .u64 t; cvta.to.shared.u64 t, %1; cvt.u32.u64 %0, t; }" : "=r"(a) : "l"(p));
    return a;
}
__device__ __forceinline__ void cp16(uint32_t sa, const void* gp) {
    asm volatile("cp.async.cg.shared.global [%0], [%1], 16;" :: "r"(sa), "l"(gp));
}
__device__ __forceinline__ void ld4(uint32_t r[4], uint32_t addr) {
    asm volatile("ldmatrix.sync.aligned.m8n8.x4.shared.b16 {%0,%1,%2,%3}, [%4];"
                 : "=r"(r[0]), "=r"(r[1]), "=r"(r[2]), "=r"(r[3]) : "r"(addr));
}
__device__ __forceinline__ void mma_h(uint32_t c[2], const uint32_t a[4],
                                      uint32_t b0, uint32_t b1) {
    asm volatile("mma.sync.aligned.m16n8k16.row.col.f16.f16.f16.f16 "
                 "{%0,%1}, {%2,%3,%4,%5}, {%6,%7}, {%0,%1};"
                 : "+r"(c[0]), "+r"(c[1])
                 : "r"(a[0]), "r"(a[1]), "r"(a[2]), "r"(a[3]), "r"(b0), "r"(b1));
}

// ------------------------- fused prep kernel -------------------------
__global__ __launch_bounds__(256) void prep_all(const float* __restrict__ x,
                                                const float* __restrict__ Wqkv,
                                                const float* __restrict__ bqkv,
                                                const float* __restrict__ Wp) {
    if (blockIdx.x < 4096) {
        size_t base = (size_t)blockIdx.x * 4096;
        float4 v[4];
#pragma unroll
        for (int j = 0; j < 4; ++j)
            v[j] = *(const float4*)(x + base + (j * 256 + threadIdx.x) * 4);
#pragma unroll
        for (int j = 0; j < 4; ++j) {
            size_t i = base + (j * 256 + threadIdx.x) * 4;
            *(__half2*)(g_xh + i)     = __floats2half2_rn(v[j].x, v[j].y);
            *(__half2*)(g_xh + i + 2) = __floats2half2_rn(v[j].z, v[j].w);
        }
    } else {
        int i = (blockIdx.x - 4096) * 256 + threadIdx.x;   // 0 .. 786431
        if (i < 1024 * 512) {
            int n = i >> 9, k = i & 511;
            int h = n >> 7, r = n & 127;
            float v;
            if (r < 64) {
                int c = h * 64 + r;
                v = (Wqkv[k * 1536 + c] - Wqkv[k * 1536 + 512 + c]) * SCALE_F;
            } else {
                int c = h * 64 + (r - 64);
                v = Wqkv[k * 1536 + 1024 + c];
            }
            g_W2h[n * 512 + k] = __float2half_rn(v);
            if (i < 512) {
                g_bz[i] = (bqkv[i] - bqkv[512 + i]) * SCALE_F;
                g_bv[i] = bqkv[1024 + i];
            }
        } else {
            int j = i - 1024 * 512;
            int n = j >> 9, k = j & 511;
            g_Wph[n * 512 + k] = __float2half_rn(Wp[k * 512 + n]);
        }
    }
}

// ------------------------- shared 128x256 mainloop pieces -------------------------
__device__ __forceinline__ void load_stage1(const __half* __restrict__ Ag,
                                            const __half* __restrict__ Bg,
                                            uint32_t stg, int kt, int tid) {
    if (kt < NKT) {
        // A: 128 rows x 4 chunks = 512 cp16
#pragma unroll
        for (int it = 0; it < 2; ++it) {
            int idx = it * 256 + tid;
            int row = idx >> 2, ch = idx & 3;
            cp16(stg + (uint32_t)(row * PITCHB + ch * 16),
                 Ag + (size_t)row * DIM + kt * 32 + ch * 8);
        }
        // B: 256 rows x 4 chunks = 1024 cp16
#pragma unroll
        for (int it = 0; it < 4; ++it) {
            int idx = it * 256 + tid;
            int row = idx >> 2, ch = idx & 3;
            cp16(stg + A1TILE + (uint32_t)(row * PITCHB + ch * 16),
                 Bg + (size_t)row * DIM + kt * 32 + ch * 8);
        }
    }
    asm volatile("cp.async.commit_group;" ::: "memory");
}

// mainloop: accumulate 64x64 per warp into c[4][8][2]
__device__ __forceinline__ void run_mainloop_w64(const __half* __restrict__ Ag,
                                                 const __half* __restrict__ Bg,
                                                 uint32_t sbase, int tid,
                                                 uint32_t aOff, uint32_t bOff,
                                                 uint32_t c[4][8][2]) {
#pragma unroll
    for (int i = 0; i < 4; ++i)
#pragma unroll
        for (int j = 0; j < 8; ++j) { c[i][j][0] = 0u; c[i][j][1] = 0u; }

    load_stage1(Ag, Bg, sbase + 0 * STAGE1, 0, tid);
    load_stage1(Ag, Bg, sbase + 1 * STAGE1, 1, tid);
    asm volatile("cp.async.wait_group 1;" ::: "memory");   // stage 0 ready
    __syncthreads();

    for (int kt = 0; kt < NKT; ++kt) {
        const uint32_t stg = sbase + (kt % NSTG1) * STAGE1;
        load_stage1(Ag, Bg, sbase + ((kt + 2) % NSTG1) * STAGE1, kt + 2, tid);
#pragma unroll
        for (int ks = 0; ks < 2; ++ks) {
            uint32_t a[4][4], b[4][4];
#pragma unroll
            for (int mm = 0; mm < 4; ++mm) ld4(a[mm], stg + aOff + mm * 16 * PITCHB + ks * 32);
#pragma unroll
            for (int pr = 0; pr < 4; ++pr) ld4(b[pr], stg + bOff + pr * 16 * PITCHB + ks * 32);
#pragma unroll
            for (int mm = 0; mm < 4; ++mm)
#pragma unroll
                for (int mn = 0; mn < 8; ++mn)
                    mma_h(c[mm][mn], a[mm], b[mn >> 1][(mn & 1) * 2],
                          b[mn >> 1][(mn & 1) * 2 + 1]);
        }
        asm volatile("cp.async.wait_group 1;" ::: "memory");   // stage kt+1 ready
        __syncthreads();
    }
    asm volatile("cp.async.wait_group 0;" ::: "memory");
    __syncthreads();
}

// ------------------------- GEMM1: 128x256 tile, softmax epilogue ------------------
__global__ __launch_bounds__(256, 2) void gemm1_kernel() {
    extern __shared__ __align__(16) unsigned char sm[];
    const int tid = threadIdx.x;
    const uint32_t sbase = smem_u32(sm);
    uint32_t c[4][8][2];

    const __half* Ag = g_xh  + (size_t)blockIdx.y * 128 * DIM;
    const __half* Bg = g_W2h + (size_t)blockIdx.x * 256 * DIM;   // 2 heads

    const int l  = tid & 31;
    const int w  = tid >> 5;
    const int wm = w >> 2;         // 0..1 (64-row half)
    const int wn = w & 3;          // 0..3 (64-col quarter: h0z, h0v, h1z, h1v)
    const uint32_t aOff = (uint32_t)((wm * 64 + (l & 15)) * PITCHB + (l >> 4) * 16);
    const uint32_t bOff = (uint32_t)(A1TILE + (wn * 64 + (l & 7) + ((l >> 4) & 1) * 8) * PITCHB
                                     + ((l >> 3) & 1) * 16);

    run_mainloop_w64(Ag, Bg, sbase, tid, aOff, bOff, c);

    // ---- epilogue: wn even = z warp (head wn>>1), wn odd = v warp ----
    const int h_l  = wn >> 1;
    const bool isZ = (wn & 1) == 0;
    const int head = blockIdx.x * 2 + h_l;

    float* Psm = (float*)sm + h_l * 128 * 68;            // [2][128][68]
    float* Zs  = (float*)(sm + 2 * 128 * 68 * 4);        // [2][128]

    if (isZ) {
        float bz2[8][2];
#pragma unroll
        for (int mn = 0; mn < 8; ++mn) {
            int cb = head * 64 + mn * 8 + 2 * (l & 3);
            bz2[mn][0] = g_bz[cb];
            bz2[mn][1] = g_bz[cb + 1];
        }
#pragma unroll
        for (int mm = 0; mm < 4; ++mm)
#pragma unroll
            for (int rh = 0; rh < 2; ++rh) {
                int r = wm * 64 + mm * 16 + rh * 8 + (l >> 2);
                float part = 0.f;
#pragma unroll
                for (int mn = 0; mn < 8; ++mn) {
                    int cb = mn * 8 + 2 * (l & 3);
                    float2 zv = __half22float2(*(const __half2*)&c[mm][mn][rh]);
                    float e0 = __expf(zv.x + bz2[mn][0]);
                    float e1 = __expf(zv.y + bz2[mn][1]);
                    part += e0 + e1;
                    *(float2*)(Psm + r * 68 + cb) = make_float2(e0, e1);
                }
                part += __shfl_xor_sync(0xffffffffu, part, 1);
                part += __shfl_xor_sync(0xffffffffu, part, 2);
                if ((l & 3) == 0) Zs[h_l * 128 + r] = part;   // full row sum (64 cols)
            }
    }
    __syncthreads();
    if (!isZ) {
        float bv2[8][2];
#pragma unroll
        for (int mn = 0; mn < 8; ++mn) {
            int cb = head * 64 + mn * 8 + 2 * (l & 3);
            bv2[mn][0] = g_bv[cb];
            bv2[mn][1] = g_bv[cb + 1];
        }
#pragma unroll
        for (int mm = 0; mm < 4; ++mm)
#pragma unroll
            for (int rh = 0; rh < 2; ++rh) {
                int r = wm * 64 + mm * 16 + rh * 8 + (l >> 2);
                float inv = 1.0f / Zs[h_l * 128 + r];
                size_t grow = (size_t)blockIdx.y * 128 + r;
                __half* op = g_Oh + grow * DIM + head * 64;
#pragma unroll
                for (int mn = 0; mn < 8; ++mn) {
                    int vc = mn * 8 + 2 * (l & 3);
                    float2 vv = __half22float2(*(const __half2*)&c[mm][mn][rh]);
                    float p0 = Psm[r * 68 + vc];
                    float p1 = Psm[r * 68 + vc + 1];
                    float o0 = p0 * inv * (vv.x + bv2[mn][0]);
                    float o1 = p1 * inv * (vv.y + bv2[mn][1]);
                    *(__half2*)(op + vc) = __floats2half2_rn(o0, o1);
                }
            }
    }
}

// ------------------------- GEMM2: 128x256 tile, +bp+x epilogue --------------------
__global__ __launch_bounds__(256, 2) void gemm2_kernel(const float* __restrict__ x,
                                                       const float* __restrict__ bp,
                                                       float* __restrict__ y) {
    extern __shared__ __align__(16) unsigned char sm[];
    const int tid = threadIdx.x;
    const uint32_t sbase = smem_u32(sm);
    uint32_t c[4][8][2];

    const __half* Ag = g_Oh  + (size_t)blockIdx.y * 128 * DIM;
    const __half* Bg = g_Wph + (size_t)blockIdx.x * 256 * DIM;

    const int l  = tid & 31;
    const int w  = tid >> 5;
    const int wm = w >> 2;         // 0..1
    const int wn = w & 3;          // 0..3 (64-col quarter)
    const uint32_t aOff = (uint32_t)((wm * 64 + (l & 15)) * PITCHB + (l >> 4) * 16);
    const uint32_t bOff = (uint32_t)(A1TILE + (wn * 64 + (l & 7) + ((l >> 4) & 1) * 8) * PITCHB
                                     + ((l >> 3) & 1) * 16);

    run_mainloop_w64(Ag, Bg, sbase, tid, aOff, bOff, c);

    const int cb0 = blockIdx.x * 256 + wn * 64;
    float2 bp2[8];
#pragma unroll
    for (int mn = 0; mn < 8; ++mn)
        bp2[mn] = *(const float2*)(bp + cb0 + mn * 8 + 2 * (l & 3));

#pragma unroll
    for (int mm = 0; mm < 4; ++mm)
#pragma unroll
        for (int rh = 0; rh < 2; ++rh) {
            int r = wm * 64 + mm * 16 + rh * 8 + (l >> 2);
            size_t grow = (size_t)blockIdx.y * 128 + r;
#pragma unroll
            for (int mn = 0; mn < 8; ++mn) {
                int col = cb0 + mn * 8 + 2 * (l & 3);
                float2 xv = *(const float2*)(x + grow * DIM + col);
                float2 av = __half22float2(*(const __half2*)&c[mm][mn][rh]);
                float2 o;
                o.x = av.x + bp2[mn].x + xv.x;
                o.y = av.y + bp2[mn].y + xv.y;
                *(float2*)(y + grow * DIM + col) = o;
            }
        }
}

// ------------------------- launch (serial, single stream) -------------------------
extern "C" void kernel_launch(void* const* d_in, const int* in_sizes, int n_in,
                              void* d_out, int out_size)
{
    const float* x    = (const float*)d_in[0];
    const float* Wqkv = (const float*)d_in[1];
    const float* bqkv = (const float*)d_in[2];
    const float* Wp   = (const float*)d_in[3];
    const float* bp   = (const float*)d_in[4];
    float* y = (float*)d_out;
    (void)in_sizes; (void)n_in; (void)out_size;

    cudaFuncSetAttribute(gemm1_kernel, cudaFuncAttributeMaxDynamicSharedMemorySize, SMEM1_BYTES);
    cudaFuncSetAttribute(gemm2_kernel, cudaFuncAttributeMaxDynamicSharedMemorySize, SMEM1_BYTES);

    prep_all<<<4096 + 3072, 256>>>(x, Wqkv, bqkv, Wp);

    dim3 g1(4, T_TOK / 128);    // head-pair fast, m-tile slow
    gemm1_kernel<<<g1, 256, SMEM1_BYTES>>>();

    dim3 g2(2, T_TOK / 128);    // n-tile fast, m-tile slow
    gemm2_kernel<<<g2, 256, SMEM1_BYTES>>>(x, bp, y);
}